// round 12
// baseline (speedup 1.0000x reference)
#include <cuda_runtime.h>
#include <cuda_fp16.h>
#include <cstdint>

// SlidingWindowAttention B=2,H=16,L=4096,D=128 fp32 io, window 2048, 4 sinks.
// R11: HMMA flash attention, no-max exp2 softmax. Tile-level software
// pipeline: softmax(s) -> ONE barrier -> interleaved QK(s+1) + PV(s) (two
// independent MMA streams). sc ping-pong (2 generations), triple-buffered
// K/V (2 CTAs/SM), one __syncthreads per tile. Sink keys via resident stub.

static constexpr int LSEQ = 4096, DIM = 128, WIN = 2048, NSINK = 4;
static constexpr int BQ = 64, BK = 64, NBH = 32;
static constexpr float SCALE2 = 0.08838834764831845f * 1.4426950408889634f;

__device__ __half g_Kh[(size_t)NBH * LSEQ * DIM];
__device__ __half g_Vh[(size_t)NBH * LSEQ * DIM];

__device__ __forceinline__ unsigned packh2(float lo, float hi) {
    unsigned r; asm("cvt.rn.f16x2.f32 %0, %1, %2;" : "=r"(r) : "f"(hi), "f"(lo));
    return r;
}

__global__ void convert_kv(const float4* __restrict__ K4,
                           const float4* __restrict__ V4) {
    int i = blockIdx.x * blockDim.x + threadIdx.x;
    int n16 = NBH * LSEQ * DIM / 16;
    if (i >= n16) return;
    uint4* ko = reinterpret_cast<uint4*>(g_Kh);
    uint4* vo = reinterpret_cast<uint4*>(g_Vh);
#pragma unroll
    for (int h = 0; h < 2; h++) {
        float4 a0 = K4[4 * i + 2 * h], a1 = K4[4 * i + 2 * h + 1];
        float4 b0 = V4[4 * i + 2 * h], b1 = V4[4 * i + 2 * h + 1];
        uint4 ku, vu;
        ku.x = packh2(a0.x, a0.y); ku.y = packh2(a0.z, a0.w);
        ku.z = packh2(a1.x, a1.y); ku.w = packh2(a1.z, a1.w);
        vu.x = packh2(b0.x, b0.y); vu.y = packh2(b0.z, b0.w);
        vu.z = packh2(b1.x, b1.y); vu.w = packh2(b1.z, b1.w);
        ko[2 * i + h] = ku;
        vo[2 * i + h] = vu;
    }
}

__device__ __forceinline__ unsigned h2ex2(unsigned x) {
    unsigned r; asm("ex2.approx.f16x2 %0, %1;" : "=r"(r) : "r"(x)); return r;
}
__device__ __forceinline__ unsigned hadd2u(unsigned a, unsigned b) {
    unsigned r; asm("add.rn.f16x2 %0, %1, %2;" : "=r"(r) : "r"(a), "r"(b));
    return r;
}
__device__ __forceinline__ float ex2f(float x) {
    float y; asm("ex2.approx.ftz.f32 %0, %1;" : "=f"(y) : "f"(x)); return y;
}
__device__ __forceinline__ void cpasync16(unsigned dst, const void* src) {
    asm volatile("cp.async.cg.shared.global [%0], [%1], 16;\n"
                 :: "r"(dst), "l"(src));
}
__device__ __forceinline__ void ldm_x4(unsigned addr, unsigned* r) {
    asm volatile("ldmatrix.sync.aligned.m8n8.x4.shared.b16 {%0,%1,%2,%3}, [%4];\n"
                 : "=r"(r[0]), "=r"(r[1]), "=r"(r[2]), "=r"(r[3]) : "r"(addr));
}
__device__ __forceinline__ void ldm_x2(unsigned addr, unsigned* r) {
    asm volatile("ldmatrix.sync.aligned.m8n8.x2.shared.b16 {%0,%1}, [%2];\n"
                 : "=r"(r[0]), "=r"(r[1]) : "r"(addr));
}
__device__ __forceinline__ void ldm_x4t(unsigned addr, unsigned* r) {
    asm volatile("ldmatrix.sync.aligned.m8n8.x4.trans.shared.b16 {%0,%1,%2,%3}, [%4];\n"
                 : "=r"(r[0]), "=r"(r[1]), "=r"(r[2]), "=r"(r[3]) : "r"(addr));
}
__device__ __forceinline__ void mma16816(float* d, const unsigned* a,
                                         unsigned b0, unsigned b1) {
    asm volatile(
        "mma.sync.aligned.m16n8k16.row.col.f32.f16.f16.f32 "
        "{%0,%1,%2,%3},{%4,%5,%6,%7},{%8,%9},{%0,%1,%2,%3};\n"
        : "+f"(d[0]), "+f"(d[1]), "+f"(d[2]), "+f"(d[3])
        : "r"(a[0]), "r"(a[1]), "r"(a[2]), "r"(a[3]), "r"(b0), "r"(b1));
}

__device__ __forceinline__ unsigned swoff(int row, int ch) {
    return (unsigned)((row << 8) + ((ch ^ (row & 7)) << 4));
}

// smem: 3 x 32KB buffers (K 16KB | V 16KB) @0/32768/65536; Q staged in buf2;
// stub K8 @98304 (2KB), V16 @100352 (4KB). Total 104448. -> 2 CTAs/SM.
static constexpr int SM_BUFSZ = 32768;
static constexpr int SM_STUBK = 98304, SM_STUBV = 100352, SMEM_TOTAL = 104448;

__global__ void __launch_bounds__(128, 2)
swa_hmma(const float* __restrict__ Q, float* __restrict__ O) {
    extern __shared__ char sm[];
    const unsigned sb = (unsigned)__cvta_generic_to_shared(sm);
    const int bh = blockIdx.y, q0 = blockIdx.x * BQ;
    const int tid = threadIdx.x, lane = tid & 31, warp = tid >> 5;
    const int gid = lane >> 2, tig = lane & 3;
    const int grp = lane >> 3, rr = lane & 7;

    const __half* Kg = g_Kh + (size_t)bh * LSEQ * DIM;
    const __half* Vg = g_Vh + (size_t)bh * LSEQ * DIM;

    const int wl = q0 - WIN + 1;
    const int t_lo = wl > 0 ? wl / BK : 0;
    const int t_hi = q0 / BK;
    const bool hasSink = t_lo > 0;
    const int nT = t_hi - t_lo + 1;

    auto loadTile = [&](int t, int buf) {
        unsigned kb = sb + (unsigned)buf * SM_BUFSZ, vb = kb + 16384u;
        const __half* kg = Kg + (size_t)(t * BK) * DIM;
        const __half* vg = Vg + (size_t)(t * BK) * DIM;
#pragma unroll
        for (int e = 0; e < 8; e++) {
            int idx = tid + e * 128;
            int row = idx >> 4, c = idx & 15;
            unsigned sw = swoff(row, c);
            cpasync16(kb + sw, kg + row * DIM + c * 8);
            cpasync16(vb + sw, vg + row * DIM + c * 8);
        }
        asm volatile("cp.async.commit_group;\n");
    };

    // ---- prologue loads: g0 = stub + tile0; g1 = tile1 (maybe empty) ----
    if (hasSink) {
        {   int row = tid >> 4, c = tid & 15;          // K[0:8]
            cpasync16(sb + SM_STUBK + swoff(row, c), Kg + row * DIM + c * 8); }
#pragma unroll
        for (int e = 0; e < 2; e++) {                  // V[0:16]
            int idx = tid + e * 128;
            int row = idx >> 4, c = idx & 15;
            cpasync16(sb + SM_STUBV + swoff(row, c), Vg + row * DIM + c * 8);
        }
    }
    loadTile(t_lo, 0);
    if (nT > 1) loadTile(t_lo + 1, 1);
    else asm volatile("cp.async.commit_group;\n");

    // stage Q (fp32 -> fp16*SCALE2) into buf2 region, grab fragments
    {
        const float* Qg0 = Q + ((size_t)bh * LSEQ + q0) * DIM;
#pragma unroll
        for (int e = 0; e < 8; e++) {
            int idx = tid + e * 128;
            int row = idx >> 4, c = idx & 15;
            const float4* s4 = (const float4*)(Qg0 + row * DIM + c * 8);
            float4 f0 = s4[0], f1 = s4[1];
            uint4 u;
            u.x = packh2(f0.x * SCALE2, f0.y * SCALE2);
            u.y = packh2(f0.z * SCALE2, f0.w * SCALE2);
            u.z = packh2(f1.x * SCALE2, f1.y * SCALE2);
            u.w = packh2(f1.z * SCALE2, f1.w * SCALE2);
            *(uint4*)(sm + 2 * SM_BUFSZ + swoff(row, c)) = u;
        }
    }
    __syncthreads();
    unsigned qa[8][4];
#pragma unroll
    for (int kc = 0; kc < 8; kc++) {
        int row = warp * 16 + ((grp & 1) << 3) + rr;
        int ch = 2 * kc + (grp >> 1);
        ldm_x4(sb + 2u * SM_BUFSZ + swoff(row, ch), qa[kc]);
    }

    // wait tile0 (g1 pending allowed), then QK(0) -> scA
    asm volatile("cp.async.wait_group 1;\n" ::);
    __syncthreads();     // also fences qa reads before buf2 reuse by load(2)

    float scA[8][4], scB[8][4];
#pragma unroll
    for (int j = 0; j < 8; j++) scA[j][0] = scA[j][1] = scA[j][2] = scA[j][3] = 0.f;
#pragma unroll
    for (int kc = 0; kc < 8; kc++) {
#pragma unroll
        for (int np = 0; np < 4; np++) {
            int row = np * 16 + ((grp >> 1) << 3) + rr;
            int ch = 2 * kc + (grp & 1);
            unsigned b[4];
            ldm_x4(sb + swoff(row, ch), b);
            mma16816(scA[2 * np],     qa[kc], b[0], b[1]);
            mma16816(scA[2 * np + 1], qa[kc], b[2], b[3]);
        }
    }

    float oc[16][4];
#pragma unroll
    for (int j = 0; j < 16; j++) oc[j][0] = oc[j][1] = oc[j][2] = oc[j][3] = 0.f;
    float l0 = 0.f, l1 = 0.f;

    const int qg0 = q0 + warp * 16 + gid, qg1 = qg0 + 8;

    // tile body: softmax(s) from scC; one barrier; load(s+2); then
    // interleaved QK(s+1)->scN + PV(s) with precomputed paAll.
    auto tileBody = [&](int s, float (&scC)[8][4], float (&scN)[8][4], int bC) {
        const int kt0 = (t_lo + s) * BK;
        const bool maskFree = (kt0 >= q0 + BQ - WIN) && (kt0 + BK - 1 <= q0);

        unsigned paAll[4][4];
        unsigned la0 = 0u, la1 = 0u;
#pragma unroll
        for (int kcc = 0; kcc < 4; kcc++) {
#pragma unroll
            for (int h = 0; h < 2; h++) {
                const int j = 2 * kcc + h;
                float s0 = scC[j][0], s1 = scC[j][1];
                float s2 = scC[j][2], s3 = scC[j][3];
                if (!maskFree) {
                    const int kg = kt0 + j * 8 + 2 * tig;
                    bool o0 = kg     <= qg0 && (kg     >= qg0 - WIN + 1 || kg     < NSINK);
                    bool o1 = kg + 1 <= qg0 && (kg + 1 >= qg0 - WIN + 1 || kg + 1 < NSINK);
                    bool o2 = kg     <= qg1 && (kg     >= qg1 - WIN + 1 || kg     < NSINK);
                    bool o3 = kg + 1 <= qg1 && (kg + 1 >= qg1 - WIN + 1 || kg + 1 < NSINK);
                    s0 = o0 ? s0 : -INFINITY; s1 = o1 ? s1 : -INFINITY;
                    s2 = o2 ? s2 : -INFINITY; s3 = o3 ? s3 : -INFINITY;
                }
                paAll[kcc][2 * h]     = h2ex2(packh2(s0, s1));
                paAll[kcc][2 * h + 1] = h2ex2(packh2(s2, s3));
                la0 = hadd2u(la0, paAll[kcc][2 * h]);
                la1 = hadd2u(la1, paAll[kcc][2 * h + 1]);
            }
        }
        {
            __half2 h0 = *reinterpret_cast<__half2*>(&la0);
            __half2 h1 = *reinterpret_cast<__half2*>(&la1);
            float2 f0 = __half22float2(h0), f1 = __half22float2(h1);
            l0 += f0.x + f0.y; l1 += f1.x + f1.y;
        }

        asm volatile("cp.async.wait_group 0;\n" ::);   // tile s+1 resident
        __syncthreads();   // single barrier: all reads of buf (s-1)%3 done

        const int bL = (bC >= 1) ? bC - 1 : 2;         // (bC+2)%3
        if (s + 2 < nT) loadTile(t_lo + s + 2, bL);

        const bool doNext = (s + 1 < nT);
        const int bN = (bC == 2) ? 0 : bC + 1;
        const unsigned kbN = sb + (unsigned)bN * SM_BUFSZ;
        const unsigned vbC = sb + (unsigned)bC * SM_BUFSZ + 16384u;

        if (doNext) {
#pragma unroll
            for (int j = 0; j < 8; j++)
                scN[j][0] = scN[j][1] = scN[j][2] = scN[j][3] = 0.f;
        }

#pragma unroll
        for (int i = 0; i < 8; i++) {                   // d-chunk i
            if (doNext) {
#pragma unroll
                for (int np = 0; np < 4; np++) {        // QK(s+1)
                    int row = np * 16 + ((grp >> 1) << 3) + rr;
                    int ch = 2 * i + (grp & 1);
                    unsigned b[4];
                    ldm_x4(kbN + swoff(row, ch), b);
                    mma16816(scN[2 * np],     qa[i], b[0], b[1]);
                    mma16816(scN[2 * np + 1], qa[i], b[2], b[3]);
                }
            }
#pragma unroll
            for (int kcc = 0; kcc < 4; kcc++) {         // PV(s)
                int row = kcc * 16 + ((grp & 1) << 3) + rr;
                int ch = 2 * i + (grp >> 1);
                unsigned v[4];
                ldm_x4t(vbC + swoff(row, ch), v);
                mma16816(oc[2 * i],     paAll[kcc], v[0], v[1]);
                mma16816(oc[2 * i + 1], paAll[kcc], v[2], v[3]);
            }
        }
    };

    int bC = 0;
    for (int s = 0; s < nT; s++) {
        if ((s & 1) == 0) tileBody(s, scA, scB, bC);
        else              tileBody(s, scB, scA, bC);
        bC = (bC == 2) ? 0 : bC + 1;
    }

    // ---- sink stub: keys 0-7 (valid < NSINK) ----
    if (hasSink) {
        float s8[4] = {0.f, 0.f, 0.f, 0.f};
#pragma unroll
        for (int kc = 0; kc < 8; kc++) {
            unsigned b[2];
            ldm_x2(sb + SM_STUBK + swoff(rr, 2 * kc + (grp & 1)), b);
            mma16816(s8, qa[kc], b[0], b[1]);
        }
        float e0 = 0.f, e1 = 0.f, e2 = 0.f, e3 = 0.f;
        if (tig < 2) {
            e0 = ex2f(s8[0]); e1 = ex2f(s8[1]);
            e2 = ex2f(s8[2]); e3 = ex2f(s8[3]);
        }
        l0 += e0 + e1; l1 += e2 + e3;
        unsigned pa[4] = {packh2(e0, e1), packh2(e2, e3), 0u, 0u};
#pragma unroll
        for (int dp = 0; dp < 8; dp++) {
            int row = ((grp & 1) << 3) + rr;
            int ch = 2 * dp + (grp >> 1);
            unsigned v[4];
            ldm_x4t(sb + SM_STUBV + swoff(row, ch), v);
            mma16816(oc[2 * dp],     pa, v[0], v[1]);
            mma16816(oc[2 * dp + 1], pa, v[2], v[3]);
        }
    }

    // epilogue: quad-reduce l, normalize, store
    l0 += __shfl_xor_sync(0xffffffffu, l0, 1);
    l0 += __shfl_xor_sync(0xffffffffu, l0, 2);
    l1 += __shfl_xor_sync(0xffffffffu, l1, 1);
    l1 += __shfl_xor_sync(0xffffffffu, l1, 2);
    const float i0 = 1.f / l0, i1 = 1.f / l1;
    float* Og = O + ((size_t)bh * LSEQ + q0) * DIM;
    const int r0 = warp * 16 + gid, r1 = r0 + 8;
#pragma unroll
    for (int j = 0; j < 16; j++) {
        int d = j * 8 + 2 * tig;
        float2 w0 = {oc[j][0] * i0, oc[j][1] * i0};
        float2 w1 = {oc[j][2] * i1, oc[j][3] * i1};
        *(float2*)(Og + (size_t)r0 * DIM + d) = w0;
        *(float2*)(Og + (size_t)r1 * DIM + d) = w1;
    }
}

extern "C" void kernel_launch(void* const* d_in, const int* in_sizes, int n_in,
                              void* d_out, int out_size) {
    const float* q = (const float*)d_in[0];
    const float* k = (const float*)d_in[1];
    const float* v = (const float*)d_in[2];
    float* o = (float*)d_out;

    int n16 = NBH * LSEQ * DIM / 16;
    convert_kv<<<n16 / 256, 256>>>((const float4*)k, (const float4*)v);

    cudaFuncSetAttribute(swa_hmma, cudaFuncAttributeMaxDynamicSharedMemorySize,
                         SMEM_TOTAL);
    dim3 grid(LSEQ / BQ, NBH);
    swa_hmma<<<grid, 128, SMEM_TOTAL>>>(q, o);
}

// round 13
// speedup vs baseline: 1.3248x; 1.3248x over previous
#include <cuda_runtime.h>
#include <cuda_fp16.h>
#include <cstdint>

// SlidingWindowAttention B=2,H=16,L=4096,D=128 fp32 io, window 2048, 4 sinks.
// R12: R6 kernel (best structure: BK=64 double-buffer, 2 barriers/tile,
// 3 CTAs/SM, f16x2 no-max exp2 softmax) + LPT scheduling: CTA x-index
// reversed so heavy (33-tile) CTAs launch first and the grid tail is made of
// light (2-tile) CTAs instead of heavy ones.

static constexpr int LSEQ = 4096, DIM = 128, WIN = 2048, NSINK = 4;
static constexpr int BQ = 64, BK = 64, NBH = 32;
static constexpr float SCALE2 = 0.08838834764831845f * 1.4426950408889634f;

__device__ __half g_Kh[(size_t)NBH * LSEQ * DIM];
__device__ __half g_Vh[(size_t)NBH * LSEQ * DIM];

__device__ __forceinline__ unsigned packh2(float lo, float hi) {
    unsigned r; asm("cvt.rn.f16x2.f32 %0, %1, %2;" : "=r"(r) : "f"(hi), "f"(lo));
    return r;
}

__global__ void convert_kv(const float4* __restrict__ K4,
                           const float4* __restrict__ V4) {
    int i = blockIdx.x * blockDim.x + threadIdx.x;   // one 32B input chunk
    int n8 = NBH * LSEQ * DIM / 8;
    if (i >= n8) return;
    float4 a0 = K4[2 * i], a1 = K4[2 * i + 1];
    float4 b0 = V4[2 * i], b1 = V4[2 * i + 1];
    uint4 ku, vu;
    ku.x = packh2(a0.x, a0.y); ku.y = packh2(a0.z, a0.w);
    ku.z = packh2(a1.x, a1.y); ku.w = packh2(a1.z, a1.w);
    vu.x = packh2(b0.x, b0.y); vu.y = packh2(b0.z, b0.w);
    vu.z = packh2(b1.x, b1.y); vu.w = packh2(b1.z, b1.w);
    reinterpret_cast<uint4*>(g_Kh)[i] = ku;
    reinterpret_cast<uint4*>(g_Vh)[i] = vu;
}

__device__ __forceinline__ unsigned h2ex2(unsigned x) {
    unsigned r; asm("ex2.approx.f16x2 %0, %1;" : "=r"(r) : "r"(x)); return r;
}
__device__ __forceinline__ unsigned hadd2u(unsigned a, unsigned b) {
    unsigned r; asm("add.rn.f16x2 %0, %1, %2;" : "=r"(r) : "r"(a), "r"(b));
    return r;
}
__device__ __forceinline__ void cpasync16(unsigned dst, const void* src) {
    asm volatile("cp.async.cg.shared.global [%0], [%1], 16;\n"
                 :: "r"(dst), "l"(src));
}
__device__ __forceinline__ void ldm_x4(unsigned addr, unsigned* r) {
    asm volatile("ldmatrix.sync.aligned.m8n8.x4.shared.b16 {%0,%1,%2,%3}, [%4];\n"
                 : "=r"(r[0]), "=r"(r[1]), "=r"(r[2]), "=r"(r[3]) : "r"(addr));
}
__device__ __forceinline__ void ldm_x4t(unsigned addr, unsigned* r) {
    asm volatile("ldmatrix.sync.aligned.m8n8.x4.trans.shared.b16 {%0,%1,%2,%3}, [%4];\n"
                 : "=r"(r[0]), "=r"(r[1]), "=r"(r[2]), "=r"(r[3]) : "r"(addr));
}
__device__ __forceinline__ void mma16816(float* d, const unsigned* a,
                                         unsigned b0, unsigned b1) {
    asm volatile(
        "mma.sync.aligned.m16n8k16.row.col.f32.f16.f16.f32 "
        "{%0,%1,%2,%3},{%4,%5,%6,%7},{%8,%9},{%0,%1,%2,%3};\n"
        : "+f"(d[0]), "+f"(d[1]), "+f"(d[2]), "+f"(d[3])
        : "r"(a[0]), "r"(a[1]), "r"(a[2]), "r"(a[3]), "r"(b0), "r"(b1));
}

__device__ __forceinline__ unsigned swoff(int row, int ch) {
    return (unsigned)((row << 8) + ((ch ^ (row & 7)) << 4));
}

__global__ void __launch_bounds__(128, 3)
swa_hmma(const float* __restrict__ Q, float* __restrict__ O) {
    extern __shared__ char sm[];
    const unsigned sb = (unsigned)__cvta_generic_to_shared(sm);
    const int bh = blockIdx.y;
    // LPT schedule: heaviest q-tiles (largest q0) first
    const int q0 = (gridDim.x - 1 - blockIdx.x) * BQ;
    const int tid = threadIdx.x, lane = tid & 31, warp = tid >> 5;
    const int gid = lane >> 2, tig = lane & 3;
    const int grp = lane >> 3, rr = lane & 7;

    const __half* Kg = g_Kh + (size_t)bh * LSEQ * DIM;
    const __half* Vg = g_Vh + (size_t)bh * LSEQ * DIM;

    const int wl = q0 - WIN + 1;
    const int t_lo = wl > 0 ? wl / BK : 0;
    const int t_hi = q0 / BK;
    const bool hasSink = t_lo > 0;
    const int nT = t_hi - t_lo + 1 + (hasSink ? 1 : 0);
    auto tileOf = [&](int s) -> int {
        return (hasSink && s == nT - 1) ? 0 : t_lo + s;
    };

    auto loadTile = [&](int kt0, int buf) {
        unsigned kb = sb + buf * 32768u, vb = kb + 16384u;
        const __half* kg = Kg + (size_t)kt0 * DIM;
        const __half* vg = Vg + (size_t)kt0 * DIM;
#pragma unroll
        for (int e = 0; e < 8; e++) {
            int idx = tid + e * 128;
            int row = idx >> 4, c = idx & 15;
            unsigned sw = swoff(row, c);
            cpasync16(kb + sw, kg + row * DIM + c * 8);
            cpasync16(vb + sw, vg + row * DIM + c * 8);
        }
        asm volatile("cp.async.commit_group;\n");
    };

    loadTile(tileOf(0) * BK, 0);

    // stage Q (fp32 -> fp16 * SCALE2) into buf1 region, grab fragments
    {
        const float* Qg0 = Q + ((size_t)bh * LSEQ + q0) * DIM;
#pragma unroll
        for (int e = 0; e < 8; e++) {
            int idx = tid + e * 128;
            int row = idx >> 4, c = idx & 15;
            const float4* s4 = (const float4*)(Qg0 + row * DIM + c * 8);
            float4 f0 = s4[0], f1 = s4[1];
            uint4 u;
            u.x = packh2(f0.x * SCALE2, f0.y * SCALE2);
            u.y = packh2(f0.z * SCALE2, f0.w * SCALE2);
            u.z = packh2(f1.x * SCALE2, f1.y * SCALE2);
            u.w = packh2(f1.z * SCALE2, f1.w * SCALE2);
            *(uint4*)(sm + 32768 + swoff(row, c)) = u;
        }
    }
    __syncthreads();
    unsigned qa[8][4];
#pragma unroll
    for (int kc = 0; kc < 8; kc++) {
        int row = warp * 16 + ((grp & 1) << 3) + rr;
        int ch = 2 * kc + (grp >> 1);
        ldm_x4(sb + 32768u + swoff(row, ch), qa[kc]);
    }
    __syncthreads();

    float oc[16][4];
#pragma unroll
    for (int j = 0; j < 16; j++) oc[j][0] = oc[j][1] = oc[j][2] = oc[j][3] = 0.f;
    float l0 = 0.f, l1 = 0.f;

    const int qg0 = q0 + warp * 16 + gid, qg1 = qg0 + 8;

    for (int s = 0; s < nT; s++) {
        const bool more = (s + 1 < nT);
        if (more) {
            loadTile(tileOf(s + 1) * BK, (s + 1) & 1);
            asm volatile("cp.async.wait_group 1;\n" ::);
        } else {
            asm volatile("cp.async.wait_group 0;\n" ::);
        }
        __syncthreads();

        const int kt0 = tileOf(s) * BK;
        const unsigned kb = sb + (unsigned)(s & 1) * 32768u, vb = kb + 16384u;
        const bool sinkTile = hasSink && s == nT - 1;
        const bool maskFree =
            !sinkTile && (kt0 >= q0 + BQ - WIN) && (kt0 + BK - 1 <= q0);

        float sc[8][4];
#pragma unroll
        for (int j = 0; j < 8; j++) sc[j][0] = sc[j][1] = sc[j][2] = sc[j][3] = 0.f;

        // S = Q * K^T (log2 domain)
#pragma unroll
        for (int kc = 0; kc < 8; kc++) {
#pragma unroll
            for (int np = 0; np < 4; np++) {
                int row = np * 16 + ((grp >> 1) << 3) + rr;
                int ch = 2 * kc + (grp & 1);
                unsigned b[4];
                ldm_x4(kb + swoff(row, ch), b);
                mma16816(sc[2 * np], qa[kc], b[0], b[1]);
                mma16816(sc[2 * np + 1], qa[kc], b[2], b[3]);
            }
        }

        // softmax in f16x2 (no max), l via HADD2, fused with PV
        unsigned la0 = 0u, la1 = 0u;
#pragma unroll
        for (int kc = 0; kc < 4; kc++) {
            unsigned pa[4];
#pragma unroll
            for (int h = 0; h < 2; h++) {
                const int j = 2 * kc + h;
                float s0 = sc[j][0], s1 = sc[j][1];
                float s2 = sc[j][2], s3 = sc[j][3];
                if (!maskFree) {
                    const int kg = kt0 + j * 8 + 2 * tig;
                    bool o0, o1, o2, o3;
                    if (sinkTile) {
                        o0 = o2 = kg < NSINK;
                        o1 = o3 = kg + 1 < NSINK;
                    } else {
                        o0 = kg     <= qg0 && (kg     >= qg0 - WIN + 1 || kg     < NSINK);
                        o1 = kg + 1 <= qg0 && (kg + 1 >= qg0 - WIN + 1 || kg + 1 < NSINK);
                        o2 = kg     <= qg1 && (kg     >= qg1 - WIN + 1 || kg     < NSINK);
                        o3 = kg + 1 <= qg1 && (kg + 1 >= qg1 - WIN + 1 || kg + 1 < NSINK);
                    }
                    s0 = o0 ? s0 : -INFINITY; s1 = o1 ? s1 : -INFINITY;
                    s2 = o2 ? s2 : -INFINITY; s3 = o3 ? s3 : -INFINITY;
                }
                pa[2 * h]     = h2ex2(packh2(s0, s1));
                pa[2 * h + 1] = h2ex2(packh2(s2, s3));
                la0 = hadd2u(la0, pa[2 * h]);
                la1 = hadd2u(la1, pa[2 * h + 1]);
            }
#pragma unroll
            for (int dp = 0; dp < 8; dp++) {
                int row = kc * 16 + ((grp & 1) << 3) + rr;
                int ch = 2 * dp + (grp >> 1);
                unsigned v[4];
                ldm_x4t(vb + swoff(row, ch), v);
                mma16816(oc[2 * dp],     pa, v[0], v[1]);
                mma16816(oc[2 * dp + 1], pa, v[2], v[3]);
            }
        }
        {
            __half2 h0 = *reinterpret_cast<__half2*>(&la0);
            __half2 h1 = *reinterpret_cast<__half2*>(&la1);
            float2 f0 = __half22float2(h0), f1 = __half22float2(h1);
            l0 += f0.x + f0.y;
            l1 += f1.x + f1.y;
        }
        __syncthreads();
    }

    // epilogue: quad-reduce l, normalize, store
    l0 += __shfl_xor_sync(0xffffffffu, l0, 1);
    l0 += __shfl_xor_sync(0xffffffffu, l0, 2);
    l1 += __shfl_xor_sync(0xffffffffu, l1, 1);
    l1 += __shfl_xor_sync(0xffffffffu, l1, 2);
    const float i0 = 1.f / l0, i1 = 1.f / l1;
    float* Og = O + ((size_t)bh * LSEQ + q0) * DIM;
    const int r0 = warp * 16 + gid, r1 = r0 + 8;
#pragma unroll
    for (int j = 0; j < 16; j++) {
        int d = j * 8 + 2 * tig;
        float2 w0 = {oc[j][0] * i0, oc[j][1] * i0};
        float2 w1 = {oc[j][2] * i1, oc[j][3] * i1};
        *(float2*)(Og + (size_t)r0 * DIM + d) = w0;
        *(float2*)(Og + (size_t)r1 * DIM + d) = w1;
    }
}

extern "C" void kernel_launch(void* const* d_in, const int* in_sizes, int n_in,
                              void* d_out, int out_size) {
    const float* q = (const float*)d_in[0];
    const float* k = (const float*)d_in[1];
    const float* v = (const float*)d_in[2];
    float* o = (float*)d_out;

    int n8 = NBH * LSEQ * DIM / 8;
    convert_kv<<<n8 / 256, 256>>>((const float4*)k, (const float4*)v);

    cudaFuncSetAttribute(swa_hmma, cudaFuncAttributeMaxDynamicSharedMemorySize,
                         65536);
    dim3 grid(LSEQ / BQ, NBH);
    swa_hmma<<<grid, 128, 65536>>>(q, o);
}